// round 11
// baseline (speedup 1.0000x reference)
#include <cuda_runtime.h>
#include <cstdint>
#include <math.h>
#include <mma.h>

using namespace nvcuda;

// ---------------- problem constants ----------------
#define BB   2
#define SS   2048
#define TT   4096          // B*S tokens
#define DD   1024
#define HH   16
#define GG   4
#define HDIM 64
#define EE   8
#define FF   4096
#define NPAIR (TT*2)

// ---------------- scratch ----------------
__device__ float g_xn [TT*DD];           // tf32-rounded
__device__ float g_q  [TT*DD];           // tf32-rounded
__device__ float g_k  [TT*GG*HDIM];      // tf32-rounded
__device__ float g_v  [TT*GG*HDIM];      // tf32-rounded
__device__ float g_o  [TT*DD];           // tf32-rounded
__device__ float g_xn2 [TT*DD];          // exact (router)
__device__ float g_xn2r[TT*DD];          // tf32-rounded (GEMM1 A)
__device__ float g_h  [(size_t)NPAIR*FF];   // tf32-rounded (gelu out)
__device__ float g_y  [(size_t)NPAIR*DD];   // exact
__device__ float g_wqr[DD*DD];
__device__ float g_wkr[DD*GG*HDIM];
__device__ float g_wvr[DD*GG*HDIM];
__device__ float g_wor[DD*DD];
__device__ float g_w1r[(size_t)EE*DD*FF];   // 134 MB
__device__ float g_w2r[(size_t)EE*FF*DD];   // 134 MB
__device__ int   g_counts[EE];
__device__ int   g_offs[EE+1];
__device__ int   g_te [NPAIR];
__device__ int   g_tr [NPAIR];
__device__ float g_tg [NPAIR];
__device__ int   g_pair[NPAIR];
__device__ int   g_slot[NPAIR];

// ---------------- helpers ----------------
__device__ __forceinline__ float gelu_tanh(float x) {
    const float c0 = 0.7978845608028654f;
    float x3 = x * x * x;
    float t = tanhf(c0 * (x + 0.044715f * x3));
    return 0.5f * x * (1.0f + t);
}

template<class Frag>
__device__ __forceinline__ void frag_to_tf32(Frag& f) {
    #pragma unroll
    for (int i = 0; i < f.num_elements; i++)
        f.x[i] = wmma::__float_to_tf32(f.x[i]);
}

__device__ __forceinline__ void cp16(void* s, const void* g) {
    unsigned int sa = (unsigned int)__cvta_generic_to_shared(s);
    asm volatile("cp.async.cg.shared.global [%0], [%1], 16;\n" :: "r"(sa), "l"(g));
}
__device__ __forceinline__ void cp16z(void* s, const void* g, bool v) {
    unsigned int sa = (unsigned int)__cvta_generic_to_shared(s);
    int sz = v ? 16 : 0;
    asm volatile("cp.async.cg.shared.global [%0], [%1], 16, %2;\n" :: "r"(sa), "l"(g), "r"(sz));
}
__device__ __forceinline__ void cp_commit() { asm volatile("cp.async.commit_group;\n"); }
template<int N> __device__ __forceinline__ void cp_wait() {
    asm volatile("cp.async.wait_group %0;\n" :: "n"(N));
}

// ---------------- fp32 -> tf32(RN) rounding pass (MLP-4) ----------------
// n4 is always a multiple of 4 here (all tensor sizes are multiples of 16 floats).
__global__ void f2tf_kernel(const float* __restrict__ in,
                            float* __restrict__ out, int n4)
{
    int base = (blockIdx.x * blockDim.x + threadIdx.x) * 4;
    int stride = gridDim.x * blockDim.x * 4;
    for (int i = base; i < n4; i += stride) {
        float4 v0 = reinterpret_cast<const float4*>(in)[i + 0];
        float4 v1 = reinterpret_cast<const float4*>(in)[i + 1];
        float4 v2 = reinterpret_cast<const float4*>(in)[i + 2];
        float4 v3 = reinterpret_cast<const float4*>(in)[i + 3];
        v0.x = wmma::__float_to_tf32(v0.x); v0.y = wmma::__float_to_tf32(v0.y);
        v0.z = wmma::__float_to_tf32(v0.z); v0.w = wmma::__float_to_tf32(v0.w);
        v1.x = wmma::__float_to_tf32(v1.x); v1.y = wmma::__float_to_tf32(v1.y);
        v1.z = wmma::__float_to_tf32(v1.z); v1.w = wmma::__float_to_tf32(v1.w);
        v2.x = wmma::__float_to_tf32(v2.x); v2.y = wmma::__float_to_tf32(v2.y);
        v2.z = wmma::__float_to_tf32(v2.z); v2.w = wmma::__float_to_tf32(v2.w);
        v3.x = wmma::__float_to_tf32(v3.x); v3.y = wmma::__float_to_tf32(v3.y);
        v3.z = wmma::__float_to_tf32(v3.z); v3.w = wmma::__float_to_tf32(v3.w);
        reinterpret_cast<float4*>(out)[i + 0] = v0;
        reinterpret_cast<float4*>(out)[i + 1] = v1;
        reinterpret_cast<float4*>(out)[i + 2] = v2;
        reinterpret_cast<float4*>(out)[i + 3] = v3;
    }
}
static inline int f2tf_grid(int n4) {
    int g = (n4 / 4 + 255) / 256;
    return g < 2368 ? g : 2368;   // cap at 16 blocks/SM
}

// ---------------- LayerNorm (ROUND: emit tf32-rounded output) ----------------
template<bool ROUND>
__global__ void ln_kernel(const float* __restrict__ x,
                          const float* __restrict__ scale,
                          const float* __restrict__ bias,
                          float* __restrict__ out)
{
    __shared__ float red[8];
    int t = blockIdx.x, tid = threadIdx.x;
    const float4* xp = reinterpret_cast<const float4*>(x + (size_t)t * DD);
    float4 v = xp[tid];
    float s = v.x + v.y + v.z + v.w;
    #pragma unroll
    for (int o = 16; o; o >>= 1) s += __shfl_xor_sync(0xffffffffu, s, o);
    if ((tid & 31) == 0) red[tid >> 5] = s;
    __syncthreads();
    if (tid < 8) {
        float r = red[tid];
        #pragma unroll
        for (int o = 4; o; o >>= 1) r += __shfl_xor_sync(0xffu, r, o);
        if (tid == 0) red[0] = r;
    }
    __syncthreads();
    float mu = red[0] * (1.0f / DD);
    float d0 = v.x - mu, d1 = v.y - mu, d2 = v.z - mu, d3 = v.w - mu;
    float sq = d0*d0 + d1*d1 + d2*d2 + d3*d3;
    #pragma unroll
    for (int o = 16; o; o >>= 1) sq += __shfl_xor_sync(0xffffffffu, sq, o);
    __syncthreads();
    if ((tid & 31) == 0) red[tid >> 5] = sq;
    __syncthreads();
    if (tid < 8) {
        float r = red[tid];
        #pragma unroll
        for (int o = 4; o; o >>= 1) r += __shfl_xor_sync(0xffu, r, o);
        if (tid == 0) red[0] = r;
    }
    __syncthreads();
    float rstd = rsqrtf(red[0] * (1.0f / DD) + 1e-6f);
    float4 sc = reinterpret_cast<const float4*>(scale)[tid];
    float4 bi = reinterpret_cast<const float4*>(bias)[tid];
    float4 o4;
    o4.x = d0 * rstd * sc.x + bi.x;
    o4.y = d1 * rstd * sc.y + bi.y;
    o4.z = d2 * rstd * sc.z + bi.z;
    o4.w = d3 * rstd * sc.w + bi.w;
    if (ROUND) {
        o4.x = wmma::__float_to_tf32(o4.x);
        o4.y = wmma::__float_to_tf32(o4.y);
        o4.z = wmma::__float_to_tf32(o4.z);
        o4.w = wmma::__float_to_tf32(o4.w);
    }
    reinterpret_cast<float4*>(out + (size_t)t * DD)[tid] = o4;
}

// ---------------- tf32 GEMM, 3-stage cp.async pipeline (true depth-2), 128x128x32 ----------------
// inputs MUST be pre-rounded to tf32 (RN); no in-register conversion.
#define BM 128
#define BN 128
#define BKT 32
#define ALD 36        // A row stride (144B)
#define BLD 132       // B row stride (528B)
#define NSTAGE 3
#define STAGE_FLOATS (128*ALD + 32*BLD)            // 8832
#define GEMM_SMEM_BYTES (NSTAGE*STAGE_FLOATS*4)    // 105984 (epilogue stage aliases stage 0)

template<int ACT, bool RESID, bool GATHER, bool SEG, bool QKV, bool ROUT>
__global__ __launch_bounds__(256, 2)
void gemm_tc(const float* __restrict__ A,
             const float* __restrict__ Bmat,
             const float* __restrict__ biasp,
             const float* __restrict__ resid,
             float* __restrict__ C,
             int M, int N, int Kd,
             const int* __restrict__ gather,
             const int* __restrict__ counts,
             const int* __restrict__ offs,
             size_t strideB, size_t strideBias,
             const float* __restrict__ B2, const float* __restrict__ bias2, float* __restrict__ C2,
             const float* __restrict__ B3, const float* __restrict__ bias3, float* __restrict__ C3)
{
    extern __shared__ float smem[];

    int off = 0, Mseg = M, Nn = N, bn;
    const float* Bm = Bmat;
    const float* bias = biasp;
    float* Cout = C;
    if (QKV) {
        int xb = blockIdx.x;
        if (xb < 8)       { bn = xb * 128; }
        else if (xb < 10) { Bm = B2; bias = bias2; Cout = C2; Nn = 256; bn = (xb - 8) * 128; }
        else              { Bm = B3; bias = bias3; Cout = C3; Nn = 256; bn = (xb - 10) * 128; }
    } else {
        bn = blockIdx.x * BN;
    }
    if (SEG) {
        int e = blockIdx.z;
        Mseg = counts[e];
        off  = offs[e];
        Bm   = Bmat + (size_t)e * strideB;
        bias = biasp + (size_t)e * strideBias;
    }
    int bm = blockIdx.y * BM;
    if (bm >= Mseg) return;

    int tid  = threadIdx.x;
    int wid  = tid >> 5;
    int lane = tid & 31;
    int wm   = wid & 3;
    int wn   = wid >> 2;

    int arow = tid >> 3;            // 0..31
    int acol = (tid & 7) * 4;       // 0..28
    const float* aptr[4];
    bool aok[4];
    #pragma unroll
    for (int p = 0; p < 4; p++) {
        int grow = bm + arow + p * 32;
        aok[p] = grow < Mseg;
        long src = 0;
        if (aok[p]) src = GATHER ? (long)gather[off + grow] : (long)(off + grow);
        aptr[p] = A + (size_t)src * Kd + acol;
    }
    int brow = tid >> 3;
    int bcol = (tid & 7) * 4;
    const float* bptr = Bm + (size_t)brow * Nn + bn + bcol;

    wmma::fragment<wmma::accumulator, 16, 16, 8, float> acc[2][4];
    #pragma unroll
    for (int i = 0; i < 2; i++)
        #pragma unroll
        for (int j = 0; j < 4; j++) wmma::fill_fragment(acc[i][j], 0.0f);

    int nk = Kd / BKT;

    // prologue: tiles 0,1 into stages 0,1 (separate commit groups)
    #pragma unroll
    for (int pt = 0; pt < 2; pt++) {
        float* Asb = smem + pt * STAGE_FLOATS;
        float* Bsb = Asb + 128 * ALD;
        int k0 = pt * BKT;
        #pragma unroll
        for (int p = 0; p < 4; p++)
            cp16z(&Asb[(arow + p * 32) * ALD + acol], aptr[p] + k0, aok[p]);
        #pragma unroll
        for (int p = 0; p < 4; p++)
            cp16(&Bsb[brow * BLD + bcol + p * 32], bptr + (size_t)k0 * Nn + p * 32);
        cp_commit();
    }

    for (int it = 0; it < nk; it++) {
        int buf = it % NSTAGE;

        // prefetch tile it+2 into stage (it+2)%3. Safe: that stage held tile
        // it-1, whose mma finished before iter it-1's trailing barrier.
        int pre = it + 2;
        if (pre < nk) {
            float* Asb = smem + (pre % NSTAGE) * STAGE_FLOATS;
            float* Bsb = Asb + 128 * ALD;
            int k0 = pre * BKT;
            #pragma unroll
            for (int p = 0; p < 4; p++)
                cp16z(&Asb[(arow + p * 32) * ALD + acol], aptr[p] + k0, aok[p]);
            #pragma unroll
            for (int p = 0; p < 4; p++)
                cp16(&Bsb[brow * BLD + bcol + p * 32], bptr + (size_t)k0 * Nn + p * 32);
        }
        cp_commit();
        cp_wait<2>();       // per-thread: tiles 0..it complete; it+1,it+2 in flight
        __syncthreads();    // cross-thread visibility of tile `it`

        float* Asb = smem + buf * STAGE_FLOATS;
        float* Bsb = Asb + 128 * ALD;
        #pragma unroll
        for (int kk = 0; kk < BKT / 8; kk++) {
            wmma::fragment<wmma::matrix_a, 16, 16, 8, wmma::precision::tf32, wmma::row_major> af[2];
            wmma::fragment<wmma::matrix_b, 16, 16, 8, wmma::precision::tf32, wmma::row_major> bf[4];
            #pragma unroll
            for (int i = 0; i < 2; i++)
                wmma::load_matrix_sync(af[i], &Asb[(wm * 32 + i * 16) * ALD + kk * 8], ALD);
            #pragma unroll
            for (int j = 0; j < 4; j++)
                wmma::load_matrix_sync(bf[j], &Bsb[(kk * 8) * BLD + wn * 64 + j * 16], BLD);
            #pragma unroll
            for (int i = 0; i < 2; i++)
                #pragma unroll
                for (int j = 0; j < 4; j++)
                    wmma::mma_sync(acc[i][j], af[i], bf[j], acc[i][j]);
        }
        __syncthreads();    // mma on stage `buf` done before iter it+1 prefetches tile it+3 into it
    }

    float* stage = smem;    // 8*256 floats, aliases dead pipeline smem (post final barrier)
    int er  = lane >> 1;
    int ec0 = (lane & 1) * 8;
    #pragma unroll
    for (int i = 0; i < 2; i++) {
        #pragma unroll
        for (int j = 0; j < 4; j++) {
            wmma::store_matrix_sync(&stage[wid * 256], acc[i][j], 16, wmma::mem_row_major);
            __syncwarp();
            int grow = bm + wm * 32 + i * 16 + er;
            if (grow < Mseg) {
                int gcol = bn + wn * 64 + j * 16 + ec0;
                size_t cidx = (size_t)(off + grow) * Nn + gcol;
                float v[8];
                #pragma unroll
                for (int q = 0; q < 4; q++) {
                    v[q]     = stage[wid * 256 + er * 16 + ec0 + q]     + bias[gcol + q];
                    v[q + 4] = stage[wid * 256 + er * 16 + ec0 + 4 + q] + bias[gcol + 4 + q];
                }
                if (ACT == 1) {
                    #pragma unroll
                    for (int q = 0; q < 8; q++) v[q] = gelu_tanh(v[q]);
                }
                if (RESID) {
                    float4 r0 = *reinterpret_cast<const float4*>(&resid[cidx]);
                    float4 r1 = *reinterpret_cast<const float4*>(&resid[cidx + 4]);
                    v[0] += r0.x; v[1] += r0.y; v[2] += r0.z; v[3] += r0.w;
                    v[4] += r1.x; v[5] += r1.y; v[6] += r1.z; v[7] += r1.w;
                }
                if (ROUT) {
                    #pragma unroll
                    for (int q = 0; q < 8; q++) v[q] = wmma::__float_to_tf32(v[q]);
                }
                *reinterpret_cast<float4*>(&Cout[cidx])     = make_float4(v[0], v[1], v[2], v[3]);
                *reinterpret_cast<float4*>(&Cout[cidx + 4]) = make_float4(v[4], v[5], v[6], v[7]);
            }
            __syncwarp();
        }
    }
}

// ---------------- attention: tf32 wmma flash, 64q x 64k tiles ----------------
// q/k/v inputs pre-rounded to tf32; only P (softmax out) needs in-reg rounding.
#define APD 68
#define ATTN_SMEM_FLOATS (6*64*APD + 4*64)

__global__ __launch_bounds__(256, 2)
void attn_tc(const float* __restrict__ qb,
             const float* __restrict__ kb,
             const float* __restrict__ vb,
             const float* __restrict__ deltas,
             const float* __restrict__ time_decay,
             float* __restrict__ ob)
{
    extern __shared__ float sm[];
    float* qs  = sm;
    float* ks  = qs  + 64 * APD;
    float* vs  = ks  + 64 * APD;
    float* ps  = vs  + 64 * APD;
    float* pvs = ps  + 64 * APD;
    float* os  = pvs + 64 * APD;
    float* dq_s = os + 64 * APD;
    float* dk_s = dq_s + 64;
    float* alpha_s = dk_s + 64;
    float* l_s = alpha_s + 64;

    int qt = blockIdx.x, h = blockIdx.y, b = blockIdx.z;
    int g = h >> 2;
    int tid = threadIdx.x;
    int wid = tid >> 5;
    float td = time_decay[h];
    float lam = (td > 20.f) ? td : log1pf(__expf(td));
    int q0 = qt * 64;

    {
        #pragma unroll
        for (int p = 0; p < 4; p++) {
            int ch = tid + p * 256;
            int r = ch >> 4, cc = (ch & 15) * 4;
            cp16(&qs[r * APD + cc],
                 qb + ((size_t)(b * SS + q0 + r)) * DD + h * HDIM + cc);
        }
        cp_commit();
    }
    if (tid < 64) dq_s[tid] = deltas[b * SS + q0 + tid];
    #pragma unroll
    for (int p = 0; p < 16; p++) {
        int idx = tid + p * 256;
        os[(idx >> 6) * APD + (idx & 63)] = 0.f;
    }
    cp_wait<0>();
    __syncthreads();

    const float scale = 0.125f;
    int rw = wid & 3;
    int cw = wid >> 2;
    int prow = tid >> 2, psub = tid & 3;
    float m_prev = -INFINITY, l_run = 0.f;

    for (int kt = 0; kt < SS / 64; kt++) {
        #pragma unroll
        for (int p = 0; p < 4; p++) {
            int ch = tid + p * 256;
            int r = ch >> 4, cc = (ch & 15) * 4;
            size_t base = ((size_t)(b * SS + kt * 64 + r)) * (GG * HDIM) + g * HDIM + cc;
            cp16(&ks[r * APD + cc], kb + base);
            cp16(&vs[r * APD + cc], vb + base);
        }
        cp_commit();
        if (tid < 64) dk_s[tid] = deltas[b * SS + kt * 64 + tid];
        cp_wait<0>();
        __syncthreads();

        {
            wmma::fragment<wmma::accumulator, 16, 16, 8, float> sacc[2];
            wmma::fill_fragment(sacc[0], 0.f);
            wmma::fill_fragment(sacc[1], 0.f);
            #pragma unroll
            for (int kk = 0; kk < 8; kk++) {
                wmma::fragment<wmma::matrix_a, 16, 16, 8, wmma::precision::tf32, wmma::row_major> af;
                wmma::fragment<wmma::matrix_b, 16, 16, 8, wmma::precision::tf32, wmma::col_major> bf[2];
                wmma::load_matrix_sync(af, &qs[(rw * 16) * APD + kk * 8], APD);
                #pragma unroll
                for (int j = 0; j < 2; j++)
                    wmma::load_matrix_sync(bf[j], &ks[(cw * 32 + j * 16) * APD + kk * 8], APD);
                #pragma unroll
                for (int j = 0; j < 2; j++)
                    wmma::mma_sync(sacc[j], af, bf[j], sacc[j]);
            }
            #pragma unroll
            for (int j = 0; j < 2; j++)
                wmma::store_matrix_sync(&ps[(rw * 16) * APD + cw * 32 + j * 16],
                                        sacc[j], APD, wmma::mem_row_major);
        }
        __syncthreads();

        {
            float dqv = dq_s[prow];
            float sv[16];
            float mt = -INFINITY;
            #pragma unroll
            for (int j = 0; j < 16; j++) {
                int c = psub * 16 + j;
                float s = ps[prow * APD + c] * scale - lam * fabsf(dqv - dk_s[c]);
                sv[j] = s;
                mt = fmaxf(mt, s);
            }
            mt = fmaxf(mt, __shfl_xor_sync(0xffffffffu, mt, 1));
            mt = fmaxf(mt, __shfl_xor_sync(0xffffffffu, mt, 2));
            float m_new = fmaxf(m_prev, mt);
            float alpha = __expf(m_prev - m_new);
            float sum = 0.f;
            #pragma unroll
            for (int j = 0; j < 16; j++) {
                float p = __expf(sv[j] - m_new);
                ps[prow * APD + psub * 16 + j] = p;
                sum += p;
            }
            sum += __shfl_xor_sync(0xffffffffu, sum, 1);
            sum += __shfl_xor_sync(0xffffffffu, sum, 2);
            l_run = l_run * alpha + sum;
            m_prev = m_new;
            if (psub == 0) alpha_s[prow] = alpha;
        }
        __syncthreads();

        {
            wmma::fragment<wmma::accumulator, 16, 16, 8, float> pacc[2];
            wmma::fill_fragment(pacc[0], 0.f);
            wmma::fill_fragment(pacc[1], 0.f);
            #pragma unroll
            for (int kk = 0; kk < 8; kk++) {
                wmma::fragment<wmma::matrix_a, 16, 16, 8, wmma::precision::tf32, wmma::row_major> af;
                wmma::fragment<wmma::matrix_b, 16, 16, 8, wmma::precision::tf32, wmma::row_major> bf[2];
                wmma::load_matrix_sync(af, &ps[(rw * 16) * APD + kk * 8], APD);
                frag_to_tf32(af);   // P is fresh fp32 -> RN round
                #pragma unroll
                for (int j = 0; j < 2; j++)
                    wmma::load_matrix_sync(bf[j], &vs[(kk * 8) * APD + cw * 32 + j * 16], APD);
                #pragma unroll
                for (int j = 0; j < 2; j++)
                    wmma::mma_sync(pacc[j], af, bf[j], pacc[j]);
            }
            #pragma unroll
            for (int j = 0; j < 2; j++)
                wmma::store_matrix_sync(&pvs[(rw * 16) * APD + cw * 32 + j * 16],
                                        pacc[j], APD, wmma::mem_row_major);
        }
        __syncthreads();

        #pragma unroll
        for (int p = 0; p < 16; p++) {
            int idx = tid + p * 256;
            int r = idx >> 6, c = idx & 63;
            os[r * APD + c] = os[r * APD + c] * alpha_s[r] + pvs[r * APD + c];
        }
        __syncthreads();
    }

    if (psub == 0) l_s[prow] = l_run;
    __syncthreads();
    #pragma unroll
    for (int p = 0; p < 16; p++) {
        int idx = tid + p * 256;
        int r = idx >> 6, c = idx & 63;
        // round: o feeds the O-projection GEMM as MMA A-operand
        ob[((size_t)(b * SS + q0 + r)) * DD + h * HDIM + c] =
            wmma::__float_to_tf32(os[r * APD + c] / l_s[r]);
    }
}

// ---------------- router + bucketing ----------------
__global__ void zero_kernel(int* counts) {
    if (threadIdx.x < EE) counts[threadIdx.x] = 0;
}

__global__ void router_kernel(const float* __restrict__ xn2,
                              const float* __restrict__ rw,
                              const float* __restrict__ rb,
                              int* __restrict__ counts,
                              int* __restrict__ te,
                              int* __restrict__ tr,
                              float* __restrict__ tg)
{
    __shared__ float lg[EE];
    int t = blockIdx.x, tid = threadIdx.x;
    int w = tid >> 5, lane = tid & 31;
    const float* xr = xn2 + (size_t)t * DD;
    float p = 0.f;
    for (int d = lane; d < DD; d += 32)
        p += xr[d] * rw[d * EE + w];
    #pragma unroll
    for (int o = 16; o; o >>= 1) p += __shfl_xor_sync(0xffffffffu, p, o);
    if (lane == 0) lg[w] = p + rb[w];
    __syncthreads();
    if (tid == 0) {
        float best = -INFINITY, second = -INFINITY;
        int i0 = 0, i1 = 0;
        #pragma unroll
        for (int e = 0; e < EE; e++) {
            float v = lg[e];
            if (v > best)        { second = best; i1 = i0; best = v; i0 = e; }
            else if (v > second) { second = v; i1 = e; }
        }
        float g0 = 1.0f / (1.0f + expf(second - best));
        float g1 = 1.0f - g0;
        int r0 = atomicAdd(&counts[i0], 1);
        int r1 = atomicAdd(&counts[i1], 1);
        te[t * 2 + 0] = i0; te[t * 2 + 1] = i1;
        tr[t * 2 + 0] = r0; tr[t * 2 + 1] = r1;
        tg[t * 2 + 0] = g0; tg[t * 2 + 1] = g1;
    }
}

__global__ void offs_kernel(const int* __restrict__ counts, int* __restrict__ offs) {
    if (threadIdx.x == 0 && blockIdx.x == 0) {
        int acc = 0;
        for (int e = 0; e < EE; e++) { offs[e] = acc; acc += counts[e]; }
        offs[EE] = acc;
    }
}

__global__ void pack_kernel(const int* __restrict__ te, const int* __restrict__ tr,
                            const int* __restrict__ offs,
                            int* __restrict__ pair, int* __restrict__ slot)
{
    int t = blockIdx.x * blockDim.x + threadIdx.x;
    if (t >= TT) return;
    #pragma unroll
    for (int k2 = 0; k2 < 2; k2++) {
        int e = te[t * 2 + k2];
        int s = offs[e] + tr[t * 2 + k2];
        pair[s] = t;
        slot[t * 2 + k2] = s;
    }
}

__global__ void combine_kernel(const int* __restrict__ slot,
                               const float* __restrict__ tg,
                               const float* __restrict__ ybuf,
                               float* __restrict__ out)
{
    int t = blockIdx.x, tid = threadIdx.x;
    int s0 = slot[t * 2], s1 = slot[t * 2 + 1];
    float g0 = tg[t * 2], g1 = tg[t * 2 + 1];
    const float4* y0 = reinterpret_cast<const float4*>(ybuf + (size_t)s0 * DD);
    const float4* y1 = reinterpret_cast<const float4*>(ybuf + (size_t)s1 * DD);
    float4* op = reinterpret_cast<float4*>(out + (size_t)t * DD);
    float4 a = op[tid], b0 = y0[tid], b1 = y1[tid];
    a.x += g0 * b0.x + g1 * b1.x;
    a.y += g0 * b0.y + g1 * b1.y;
    a.z += g0 * b0.z + g1 * b1.z;
    a.w += g0 * b0.w + g1 * b1.w;
    op[tid] = a;
}

// ---------------- launch ----------------
extern "C" void kernel_launch(void* const* d_in, const int* in_sizes, int n_in,
                              void* d_out, int out_size)
{
    const float* x      = (const float*)d_in[0];
    const float* deltas = (const float*)d_in[1];
    const float* ln1_s  = (const float*)d_in[2];
    const float* ln1_b  = (const float*)d_in[3];
    const float* wq     = (const float*)d_in[4];
    const float* bq     = (const float*)d_in[5];
    const float* wk     = (const float*)d_in[6];
    const float* bk     = (const float*)d_in[7];
    const float* wv     = (const float*)d_in[8];
    const float* bv     = (const float*)d_in[9];
    const float* wo     = (const float*)d_in[10];
    const float* bo     = (const float*)d_in[11];
    const float* tdcy   = (const float*)d_in[12];
    const float* ln2_s  = (const float*)d_in[13];
    const float* ln2_b  = (const float*)d_in[14];
    const float* rw     = (const float*)d_in[15];
    const float* rb     = (const float*)d_in[16];
    const float* w1     = (const float*)d_in[17];
    const float* b1     = (const float*)d_in[18];
    const float* w2     = (const float*)d_in[19];
    const float* b2     = (const float*)d_in[20];
    float* out = (float*)d_out;

    float *p_xn, *p_q, *p_k, *p_v, *p_o, *p_xn2, *p_xn2r, *p_h, *p_y, *p_tg;
    float *p_wqr, *p_wkr, *p_wvr, *p_wor, *p_w1r, *p_w2r;
    int *p_counts, *p_offs, *p_te, *p_tr, *p_pair, *p_slot;
    cudaGetSymbolAddress((void**)&p_xn,  g_xn);
    cudaGetSymbolAddress((void**)&p_q,   g_q);
    cudaGetSymbolAddress((void**)&p_k,   g_k);
    cudaGetSymbolAddress((void**)&p_v,   g_v);
    cudaGetSymbolAddress((void**)&p_o,   g_o);
    cudaGetSymbolAddress((void**)&p_xn2, g_xn2);
    cudaGetSymbolAddress((void**)&p_xn2r, g_xn2r);
    cudaGetSymbolAddress((void**)&p_h,   g_h);
    cudaGetSymbolAddress((void**)&p_y,   g_y);
    cudaGetSymbolAddress((void**)&p_wqr, g_wqr);
    cudaGetSymbolAddress((void**)&p_wkr, g_wkr);
    cudaGetSymbolAddress((void**)&p_wvr, g_wvr);
    cudaGetSymbolAddress((void**)&p_wor, g_wor);
    cudaGetSymbolAddress((void**)&p_w1r, g_w1r);
    cudaGetSymbolAddress((void**)&p_w2r, g_w2r);
    cudaGetSymbolAddress((void**)&p_counts, g_counts);
    cudaGetSymbolAddress((void**)&p_offs,   g_offs);
    cudaGetSymbolAddress((void**)&p_te,     g_te);
    cudaGetSymbolAddress((void**)&p_tr,     g_tr);
    cudaGetSymbolAddress((void**)&p_tg,     g_tg);
    cudaGetSymbolAddress((void**)&p_pair,   g_pair);
    cudaGetSymbolAddress((void**)&p_slot,   g_slot);

    const int GEMM_SMEM = GEMM_SMEM_BYTES;
    const int ATTN_SMEM = ATTN_SMEM_FLOATS * (int)sizeof(float);
    static bool attr_done = false;
    if (!attr_done) {
        cudaFuncSetAttribute(gemm_tc<0, false, false, false, true,  true >,
                             cudaFuncAttributeMaxDynamicSharedMemorySize, GEMM_SMEM);
        cudaFuncSetAttribute(gemm_tc<0, true,  false, false, false, false>,
                             cudaFuncAttributeMaxDynamicSharedMemorySize, GEMM_SMEM);
        cudaFuncSetAttribute(gemm_tc<1, false, true,  true,  false, true >,
                             cudaFuncAttributeMaxDynamicSharedMemorySize, GEMM_SMEM);
        cudaFuncSetAttribute(gemm_tc<0, false, false, true,  false, false>,
                             cudaFuncAttributeMaxDynamicSharedMemorySize, GEMM_SMEM);
        cudaFuncSetAttribute(attn_tc,
                             cudaFuncAttributeMaxDynamicSharedMemorySize, ATTN_SMEM);
        attr_done = true;
    }

    // 0) pre-round all weights to tf32 (RN)
    f2tf_kernel<<<f2tf_grid(DD * DD / 4), 256>>>(wq, p_wqr, DD * DD / 4);
    f2tf_kernel<<<f2tf_grid(DD * GG * HDIM / 4), 256>>>(wk, p_wkr, DD * GG * HDIM / 4);
    f2tf_kernel<<<f2tf_grid(DD * GG * HDIM / 4), 256>>>(wv, p_wvr, DD * GG * HDIM / 4);
    f2tf_kernel<<<f2tf_grid(DD * DD / 4), 256>>>(wo, p_wor, DD * DD / 4);
    f2tf_kernel<<<f2tf_grid(EE * DD * FF / 4), 256>>>(w1, p_w1r, EE * DD * FF / 4);
    f2tf_kernel<<<f2tf_grid(EE * FF * DD / 4), 256>>>(w2, p_w2r, EE * FF * DD / 4);
    // 1) LN1 (rounded output: feeds QKV GEMM only)
    ln_kernel<true><<<TT, 256>>>(x, ln1_s, ln1_b, p_xn);
    // 2) fused Q/K/V projection (outputs rounded for attention MMA)
    gemm_tc<0, false, false, false, true, true><<<dim3(12, TT / BM, 1), 256, GEMM_SMEM>>>(
        p_xn, p_wqr, bq, nullptr, p_q, TT, DD, DD, nullptr, nullptr, nullptr, 0, 0,
        p_wkr, bk, p_k, p_wvr, bv, p_v);
    // 3) attention (output rounded for O-proj)
    attn_tc<<<dim3(SS / 64, HH, BB), 256, ATTN_SMEM>>>(p_q, p_k, p_v, deltas, tdcy, p_o);
    // 4) output projection + residual (exact out)
    gemm_tc<0, true, false, false, false, false><<<dim3(DD / BN, TT / BM, 1), 256, GEMM_SMEM>>>(
        p_o, p_wor, bo, x, out, TT, DD, DD, nullptr, nullptr, nullptr, 0, 0,
        nullptr, nullptr, nullptr, nullptr, nullptr, nullptr);
    // 5) LN2 exact (router) + rounded copy (GEMM1 A)
    ln_kernel<false><<<TT, 256>>>(out, ln2_s, ln2_b, p_xn2);
    f2tf_kernel<<<f2tf_grid(TT * DD / 4), 256>>>(p_xn2, p_xn2r, TT * DD / 4);
    // 6) router + bucketing
    zero_kernel<<<1, 32>>>(p_counts);
    router_kernel<<<TT, 256>>>(p_xn2, rw, rb, p_counts, p_te, p_tr, p_tg);
    offs_kernel<<<1, 1>>>(p_counts, p_offs);
    pack_kernel<<<TT / 256, 256>>>(p_te, p_tr, p_offs, p_pair, p_slot);
    // 7) expert GEMM1 (gathered, gelu, rounded h out)
    gemm_tc<1, false, true, true, false, true><<<dim3(FF / BN, NPAIR / BM, EE), 256, GEMM_SMEM>>>(
        p_xn2r, p_w1r, b1, nullptr, p_h, 0, FF, DD, p_pair, p_counts, p_offs,
        (size_t)DD * FF, (size_t)FF,
        nullptr, nullptr, nullptr, nullptr, nullptr, nullptr);
    // 8) expert GEMM2 (exact y out)
    gemm_tc<0, false, false, true, false, false><<<dim3(DD / BN, NPAIR / BM, EE), 256, GEMM_SMEM>>>(
        p_h, p_w2r, b2, nullptr, p_y, 0, DD, FF, nullptr, p_counts, p_offs,
        (size_t)FF * DD, (size_t)DD,
        nullptr, nullptr, nullptr, nullptr, nullptr, nullptr);
    // 9) combine
    combine_kernel<<<TT, 256>>>(p_slot, p_tg, p_y, out);

    (void)in_sizes; (void)n_in; (void)out_size;
}

// round 12
// speedup vs baseline: 1.0670x; 1.0670x over previous
#include <cuda_runtime.h>
#include <cstdint>
#include <math.h>
#include <mma.h>

using namespace nvcuda;

// ---------------- problem constants ----------------
#define BB   2
#define SS   2048
#define TT   4096          // B*S tokens
#define DD   1024
#define HH   16
#define GG   4
#define HDIM 64
#define EE   8
#define FF   4096
#define NPAIR (TT*2)

// ---------------- scratch ----------------
__device__ float g_xn [TT*DD];           // tf32-rounded
__device__ float g_q  [TT*DD];           // tf32-rounded
__device__ float g_k  [TT*GG*HDIM];      // tf32-rounded
__device__ float g_v  [TT*GG*HDIM];      // tf32-rounded
__device__ float g_o  [TT*DD];           // tf32-rounded
__device__ float g_xn2 [TT*DD];          // exact (router)
__device__ float g_xn2r[TT*DD];          // tf32-rounded (GEMM1 A)
__device__ float g_h  [(size_t)NPAIR*FF];   // tf32-rounded (gelu out)
__device__ float g_y  [(size_t)NPAIR*DD];   // exact
__device__ float g_wqr[DD*DD];
__device__ float g_wkr[DD*GG*HDIM];
__device__ float g_wvr[DD*GG*HDIM];
__device__ float g_wor[DD*DD];
__device__ int   g_counts[EE];
__device__ int   g_offs[EE+1];
__device__ int   g_te [NPAIR];
__device__ int   g_tr [NPAIR];
__device__ float g_tg [NPAIR];
__device__ int   g_pair[NPAIR];
__device__ int   g_slot[NPAIR];

// ---------------- helpers ----------------
__device__ __forceinline__ float gelu_tanh(float x) {
    const float c0 = 0.7978845608028654f;
    float x3 = x * x * x;
    float t = tanhf(c0 * (x + 0.044715f * x3));
    return 0.5f * x * (1.0f + t);
}

template<class Frag>
__device__ __forceinline__ void frag_to_tf32(Frag& f) {
    #pragma unroll
    for (int i = 0; i < f.num_elements; i++)
        f.x[i] = wmma::__float_to_tf32(f.x[i]);
}

__device__ __forceinline__ void cp16(void* s, const void* g) {
    unsigned int sa = (unsigned int)__cvta_generic_to_shared(s);
    asm volatile("cp.async.cg.shared.global [%0], [%1], 16;\n" :: "r"(sa), "l"(g));
}
__device__ __forceinline__ void cp16z(void* s, const void* g, bool v) {
    unsigned int sa = (unsigned int)__cvta_generic_to_shared(s);
    int sz = v ? 16 : 0;
    asm volatile("cp.async.cg.shared.global [%0], [%1], 16, %2;\n" :: "r"(sa), "l"(g), "r"(sz));
}
__device__ __forceinline__ void cp_commit() { asm volatile("cp.async.commit_group;\n"); }
template<int N> __device__ __forceinline__ void cp_wait() {
    asm volatile("cp.async.wait_group %0;\n" :: "n"(N));
}

// ---------------- fp32 -> tf32(RN) rounding pass ----------------
__global__ void f2tf_kernel(const float* __restrict__ in,
                            float* __restrict__ out, int n4)
{
    int i = blockIdx.x * blockDim.x + threadIdx.x;
    if (i >= n4) return;
    float4 v = reinterpret_cast<const float4*>(in)[i];
    v.x = wmma::__float_to_tf32(v.x);
    v.y = wmma::__float_to_tf32(v.y);
    v.z = wmma::__float_to_tf32(v.z);
    v.w = wmma::__float_to_tf32(v.w);
    reinterpret_cast<float4*>(out)[i] = v;
}

// ---------------- LayerNorm (ROUND: emit tf32-rounded output) ----------------
template<bool ROUND>
__global__ void ln_kernel(const float* __restrict__ x,
                          const float* __restrict__ scale,
                          const float* __restrict__ bias,
                          float* __restrict__ out)
{
    __shared__ float red[8];
    int t = blockIdx.x, tid = threadIdx.x;
    const float4* xp = reinterpret_cast<const float4*>(x + (size_t)t * DD);
    float4 v = xp[tid];
    float s = v.x + v.y + v.z + v.w;
    #pragma unroll
    for (int o = 16; o; o >>= 1) s += __shfl_xor_sync(0xffffffffu, s, o);
    if ((tid & 31) == 0) red[tid >> 5] = s;
    __syncthreads();
    if (tid < 8) {
        float r = red[tid];
        #pragma unroll
        for (int o = 4; o; o >>= 1) r += __shfl_xor_sync(0xffu, r, o);
        if (tid == 0) red[0] = r;
    }
    __syncthreads();
    float mu = red[0] * (1.0f / DD);
    float d0 = v.x - mu, d1 = v.y - mu, d2 = v.z - mu, d3 = v.w - mu;
    float sq = d0*d0 + d1*d1 + d2*d2 + d3*d3;
    #pragma unroll
    for (int o = 16; o; o >>= 1) sq += __shfl_xor_sync(0xffffffffu, sq, o);
    __syncthreads();
    if ((tid & 31) == 0) red[tid >> 5] = sq;
    __syncthreads();
    if (tid < 8) {
        float r = red[tid];
        #pragma unroll
        for (int o = 4; o; o >>= 1) r += __shfl_xor_sync(0xffu, r, o);
        if (tid == 0) red[0] = r;
    }
    __syncthreads();
    float rstd = rsqrtf(red[0] * (1.0f / DD) + 1e-6f);
    float4 sc = reinterpret_cast<const float4*>(scale)[tid];
    float4 bi = reinterpret_cast<const float4*>(bias)[tid];
    float4 o4;
    o4.x = d0 * rstd * sc.x + bi.x;
    o4.y = d1 * rstd * sc.y + bi.y;
    o4.z = d2 * rstd * sc.z + bi.z;
    o4.w = d3 * rstd * sc.w + bi.w;
    if (ROUND) {
        o4.x = wmma::__float_to_tf32(o4.x);
        o4.y = wmma::__float_to_tf32(o4.y);
        o4.z = wmma::__float_to_tf32(o4.z);
        o4.w = wmma::__float_to_tf32(o4.w);
    }
    reinterpret_cast<float4*>(out + (size_t)t * DD)[tid] = o4;
}

// ---------------- tf32 GEMM, cp.async double-buffered, 128x128x32 (round-8 champion) ----------------
// A operands MUST be pre-rounded to tf32 (RN). B: pre-rounded unless CVTB (in-frag RN).
#define BM 128
#define BN 128
#define BKT 32
#define ALD 40
#define BLD 136
#define GEMM_SMEM_FLOATS (2*128*ALD + 2*32*BLD + 8*256)

template<int ACT, bool RESID, bool GATHER, bool SEG, bool QKV, bool ROUT, bool CVTB>
__global__ __launch_bounds__(256, 2)
void gemm_tc(const float* __restrict__ A,
             const float* __restrict__ Bmat,
             const float* __restrict__ biasp,
             const float* __restrict__ resid,
             float* __restrict__ C,
             int M, int N, int Kd,
             const int* __restrict__ gather,
             const int* __restrict__ counts,
             const int* __restrict__ offs,
             size_t strideB, size_t strideBias,
             const float* __restrict__ B2, const float* __restrict__ bias2, float* __restrict__ C2,
             const float* __restrict__ B3, const float* __restrict__ bias3, float* __restrict__ C3)
{
    extern __shared__ float smem[];
    float* As    = smem;                       // [2][128][ALD]
    float* Bs    = As + 2 * 128 * ALD;         // [2][32][BLD]
    float* stage = Bs + 2 * 32 * BLD;          // [8][256]

    int off = 0, Mseg = M, Nn = N, bn;
    const float* Bm = Bmat;
    const float* bias = biasp;
    float* Cout = C;
    if (QKV) {
        int xb = blockIdx.x;
        if (xb < 8)       { bn = xb * 128; }
        else if (xb < 10) { Bm = B2; bias = bias2; Cout = C2; Nn = 256; bn = (xb - 8) * 128; }
        else              { Bm = B3; bias = bias3; Cout = C3; Nn = 256; bn = (xb - 10) * 128; }
    } else {
        bn = blockIdx.x * BN;
    }
    if (SEG) {
        int e = blockIdx.z;
        Mseg = counts[e];
        off  = offs[e];
        Bm   = Bmat + (size_t)e * strideB;
        bias = biasp + (size_t)e * strideBias;
    }
    int bm = blockIdx.y * BM;
    if (bm >= Mseg) return;

    int tid  = threadIdx.x;
    int wid  = tid >> 5;
    int lane = tid & 31;
    int wm   = wid & 3;
    int wn   = wid >> 2;

    int arow = tid >> 3;            // 0..31
    int acol = (tid & 7) * 4;       // 0..28
    const float* aptr[4];
    bool aok[4];
    #pragma unroll
    for (int p = 0; p < 4; p++) {
        int grow = bm + arow + p * 32;
        aok[p] = grow < Mseg;
        long src = 0;
        if (aok[p]) src = GATHER ? (long)gather[off + grow] : (long)(off + grow);
        aptr[p] = A + (size_t)src * Kd + acol;
    }
    int brow = tid >> 3;
    int bcol = (tid & 7) * 4;
    const float* bptr = Bm + (size_t)brow * Nn + bn + bcol;

    wmma::fragment<wmma::accumulator, 16, 16, 8, float> acc[2][4];
    #pragma unroll
    for (int i = 0; i < 2; i++)
        #pragma unroll
        for (int j = 0; j < 4; j++) wmma::fill_fragment(acc[i][j], 0.0f);

    int nk = Kd / BKT;

    {
        #pragma unroll
        for (int p = 0; p < 4; p++)
            cp16z(&As[(0 * 128 + arow + p * 32) * ALD + acol], aptr[p], aok[p]);
        #pragma unroll
        for (int p = 0; p < 4; p++)
            cp16(&Bs[(0 * 32 + brow) * BLD + bcol + p * 32], bptr + p * 32);
        cp_commit();
    }

    for (int it = 0; it < nk; it++) {
        int buf = it & 1;
        if (it + 1 < nk) {
            int k0 = (it + 1) * BKT;
            int nb = buf ^ 1;
            #pragma unroll
            for (int p = 0; p < 4; p++)
                cp16z(&As[(nb * 128 + arow + p * 32) * ALD + acol], aptr[p] + k0, aok[p]);
            #pragma unroll
            for (int p = 0; p < 4; p++)
                cp16(&Bs[(nb * 32 + brow) * BLD + bcol + p * 32],
                     bptr + (size_t)k0 * Nn + p * 32);
        }
        cp_commit();
        cp_wait<1>();
        __syncthreads();

        #pragma unroll
        for (int kk = 0; kk < BKT / 8; kk++) {
            wmma::fragment<wmma::matrix_a, 16, 16, 8, wmma::precision::tf32, wmma::row_major> af[2];
            wmma::fragment<wmma::matrix_b, 16, 16, 8, wmma::precision::tf32, wmma::row_major> bf[4];
            #pragma unroll
            for (int i = 0; i < 2; i++)
                wmma::load_matrix_sync(af[i], &As[(buf * 128 + wm * 32 + i * 16) * ALD + kk * 8], ALD);
            #pragma unroll
            for (int j = 0; j < 4; j++) {
                wmma::load_matrix_sync(bf[j], &Bs[(buf * 32 + kk * 8) * BLD + wn * 64 + j * 16], BLD);
                if (CVTB) frag_to_tf32(bf[j]);
            }
            #pragma unroll
            for (int i = 0; i < 2; i++)
                #pragma unroll
                for (int j = 0; j < 4; j++)
                    wmma::mma_sync(acc[i][j], af[i], bf[j], acc[i][j]);
        }
        __syncthreads();
    }

    int er  = lane >> 1;
    int ec0 = (lane & 1) * 8;
    #pragma unroll
    for (int i = 0; i < 2; i++) {
        #pragma unroll
        for (int j = 0; j < 4; j++) {
            wmma::store_matrix_sync(&stage[wid * 256], acc[i][j], 16, wmma::mem_row_major);
            __syncwarp();
            int grow = bm + wm * 32 + i * 16 + er;
            if (grow < Mseg) {
                int gcol = bn + wn * 64 + j * 16 + ec0;
                size_t cidx = (size_t)(off + grow) * Nn + gcol;
                float v[8];
                #pragma unroll
                for (int q = 0; q < 4; q++) {
                    v[q]     = stage[wid * 256 + er * 16 + ec0 + q]     + bias[gcol + q];
                    v[q + 4] = stage[wid * 256 + er * 16 + ec0 + 4 + q] + bias[gcol + 4 + q];
                }
                if (ACT == 1) {
                    #pragma unroll
                    for (int q = 0; q < 8; q++) v[q] = gelu_tanh(v[q]);
                }
                if (RESID) {
                    float4 r0 = *reinterpret_cast<const float4*>(&resid[cidx]);
                    float4 r1 = *reinterpret_cast<const float4*>(&resid[cidx + 4]);
                    v[0] += r0.x; v[1] += r0.y; v[2] += r0.z; v[3] += r0.w;
                    v[4] += r1.x; v[5] += r1.y; v[6] += r1.z; v[7] += r1.w;
                }
                if (ROUT) {
                    #pragma unroll
                    for (int q = 0; q < 8; q++) v[q] = wmma::__float_to_tf32(v[q]);
                }
                *reinterpret_cast<float4*>(&Cout[cidx])     = make_float4(v[0], v[1], v[2], v[3]);
                *reinterpret_cast<float4*>(&Cout[cidx + 4]) = make_float4(v[4], v[5], v[6], v[7]);
            }
            __syncwarp();
        }
    }
}

// ---------------- attention: tf32 wmma flash, 64q x 64k tiles ----------------
// q/k/v pre-rounded. PV accumulates directly into os (acc loaded from smem).
#define APD 68
#define ATTN_SMEM_FLOATS (5*64*APD + 4*64)

__global__ __launch_bounds__(256, 2)
void attn_tc(const float* __restrict__ qb,
             const float* __restrict__ kb,
             const float* __restrict__ vb,
             const float* __restrict__ deltas,
             const float* __restrict__ time_decay,
             float* __restrict__ ob)
{
    extern __shared__ float sm[];
    float* qs  = sm;
    float* ks  = qs  + 64 * APD;
    float* vs  = ks  + 64 * APD;
    float* ps  = vs  + 64 * APD;
    float* os  = ps  + 64 * APD;
    float* dq_s = os + 64 * APD;
    float* dk_s = dq_s + 64;
    float* alpha_s = dk_s + 64;
    float* l_s = alpha_s + 64;

    int qt = blockIdx.x, h = blockIdx.y, b = blockIdx.z;
    int g = h >> 2;
    int tid = threadIdx.x;
    int wid = tid >> 5;
    float td = time_decay[h];
    float lam = (td > 20.f) ? td : log1pf(__expf(td));
    int q0 = qt * 64;

    {
        #pragma unroll
        for (int p = 0; p < 4; p++) {
            int ch = tid + p * 256;
            int r = ch >> 4, cc = (ch & 15) * 4;
            cp16(&qs[r * APD + cc],
                 qb + ((size_t)(b * SS + q0 + r)) * DD + h * HDIM + cc);
        }
        cp_commit();
    }
    if (tid < 64) dq_s[tid] = deltas[b * SS + q0 + tid];
    #pragma unroll
    for (int p = 0; p < 16; p++) {
        int idx = tid + p * 256;
        os[(idx >> 6) * APD + (idx & 63)] = 0.f;
    }
    cp_wait<0>();
    __syncthreads();

    const float scale = 0.125f;
    int rw = wid & 3;
    int cw = wid >> 2;
    int prow = tid >> 2, psub = tid & 3;
    float m_prev = -INFINITY, l_run = 0.f;

    for (int kt = 0; kt < SS / 64; kt++) {
        // previous iteration's trailing barrier guarantees PV mma done before overwrite
        #pragma unroll
        for (int p = 0; p < 4; p++) {
            int ch = tid + p * 256;
            int r = ch >> 4, cc = (ch & 15) * 4;
            size_t base = ((size_t)(b * SS + kt * 64 + r)) * (GG * HDIM) + g * HDIM + cc;
            cp16(&ks[r * APD + cc], kb + base);
            cp16(&vs[r * APD + cc], vb + base);
        }
        cp_commit();
        if (tid < 64) dk_s[tid] = deltas[b * SS + kt * 64 + tid];
        cp_wait<0>();
        __syncthreads();

        // S = Q @ K^T
        {
            wmma::fragment<wmma::accumulator, 16, 16, 8, float> sacc[2];
            wmma::fill_fragment(sacc[0], 0.f);
            wmma::fill_fragment(sacc[1], 0.f);
            #pragma unroll
            for (int kk = 0; kk < 8; kk++) {
                wmma::fragment<wmma::matrix_a, 16, 16, 8, wmma::precision::tf32, wmma::row_major> af;
                wmma::fragment<wmma::matrix_b, 16, 16, 8, wmma::precision::tf32, wmma::col_major> bf[2];
                wmma::load_matrix_sync(af, &qs[(rw * 16) * APD + kk * 8], APD);
                #pragma unroll
                for (int j = 0; j < 2; j++)
                    wmma::load_matrix_sync(bf[j], &ks[(cw * 32 + j * 16) * APD + kk * 8], APD);
                #pragma unroll
                for (int j = 0; j < 2; j++)
                    wmma::mma_sync(sacc[j], af, bf[j], sacc[j]);
            }
            #pragma unroll
            for (int j = 0; j < 2; j++)
                wmma::store_matrix_sync(&ps[(rw * 16) * APD + cw * 32 + j * 16],
                                        sacc[j], APD, wmma::mem_row_major);
        }
        __syncthreads();

        // softmax + alpha-scale of os (thread owns row prow, cols psub*16..+15)
        {
            float dqv = dq_s[prow];
            float sv[16];
            float mt = -INFINITY;
            #pragma unroll
            for (int j = 0; j < 16; j++) {
                int c = psub * 16 + j;
                float s = ps[prow * APD + c] * scale - lam * fabsf(dqv - dk_s[c]);
                sv[j] = s;
                mt = fmaxf(mt, s);
            }
            mt = fmaxf(mt, __shfl_xor_sync(0xffffffffu, mt, 1));
            mt = fmaxf(mt, __shfl_xor_sync(0xffffffffu, mt, 2));
            float m_new = fmaxf(m_prev, mt);
            float alpha = __expf(m_prev - m_new);
            float sum = 0.f;
            #pragma unroll
            for (int j = 0; j < 16; j++) {
                float p = __expf(sv[j] - m_new);
                ps[prow * APD + psub * 16 + j] = p;
                sum += p;
            }
            sum += __shfl_xor_sync(0xffffffffu, sum, 1);
            sum += __shfl_xor_sync(0xffffffffu, sum, 2);
            l_run = l_run * alpha + sum;
            m_prev = m_new;
            // scale O rows by alpha in-place
            #pragma unroll
            for (int j = 0; j < 16; j++)
                os[prow * APD + psub * 16 + j] *= alpha;
        }
        __syncthreads();

        // os += P @ V (accumulator loaded from / stored to os)
        {
            wmma::fragment<wmma::accumulator, 16, 16, 8, float> pacc[2];
            #pragma unroll
            for (int j = 0; j < 2; j++)
                wmma::load_matrix_sync(pacc[j], &os[(rw * 16) * APD + cw * 32 + j * 16],
                                       APD, wmma::mem_row_major);
            #pragma unroll
            for (int kk = 0; kk < 8; kk++) {
                wmma::fragment<wmma::matrix_a, 16, 16, 8, wmma::precision::tf32, wmma::row_major> af;
                wmma::fragment<wmma::matrix_b, 16, 16, 8, wmma::precision::tf32, wmma::row_major> bf[2];
                wmma::load_matrix_sync(af, &ps[(rw * 16) * APD + kk * 8], APD);
                frag_to_tf32(af);   // P is fresh fp32 -> RN round
                #pragma unroll
                for (int j = 0; j < 2; j++)
                    wmma::load_matrix_sync(bf[j], &vs[(kk * 8) * APD + cw * 32 + j * 16], APD);
                #pragma unroll
                for (int j = 0; j < 2; j++)
                    wmma::mma_sync(pacc[j], af, bf[j], pacc[j]);
            }
            #pragma unroll
            for (int j = 0; j < 2; j++)
                wmma::store_matrix_sync(&os[(rw * 16) * APD + cw * 32 + j * 16],
                                        pacc[j], APD, wmma::mem_row_major);
        }
        __syncthreads();
    }

    if (psub == 0) l_s[prow] = l_run;
    __syncthreads();
    #pragma unroll
    for (int p = 0; p < 16; p++) {
        int idx = tid + p * 256;
        int r = idx >> 6, c = idx & 63;
        ob[((size_t)(b * SS + q0 + r)) * DD + h * HDIM + c] =
            wmma::__float_to_tf32(os[r * APD + c] / l_s[r]);
    }
}

// ---------------- router + bucketing ----------------
__global__ void zero_kernel(int* counts) {
    if (threadIdx.x < EE) counts[threadIdx.x] = 0;
}

__global__ void router_kernel(const float* __restrict__ xn2,
                              const float* __restrict__ rw,
                              const float* __restrict__ rb,
                              int* __restrict__ counts,
                              int* __restrict__ te,
                              int* __restrict__ tr,
                              float* __restrict__ tg)
{
    __shared__ float lg[EE];
    int t = blockIdx.x, tid = threadIdx.x;
    int w = tid >> 5, lane = tid & 31;
    const float* xr = xn2 + (size_t)t * DD;
    float p = 0.f;
    for (int d = lane; d < DD; d += 32)
        p += xr[d] * rw[d * EE + w];
    #pragma unroll
    for (int o = 16; o; o >>= 1) p += __shfl_xor_sync(0xffffffffu, p, o);
    if (lane == 0) lg[w] = p + rb[w];
    __syncthreads();
    if (tid == 0) {
        float best = -INFINITY, second = -INFINITY;
        int i0 = 0, i1 = 0;
        #pragma unroll
        for (int e = 0; e < EE; e++) {
            float v = lg[e];
            if (v > best)        { second = best; i1 = i0; best = v; i0 = e; }
            else if (v > second) { second = v; i1 = e; }
        }
        float g0 = 1.0f / (1.0f + expf(second - best));
        float g1 = 1.0f - g0;
        int r0 = atomicAdd(&counts[i0], 1);
        int r1 = atomicAdd(&counts[i1], 1);
        te[t * 2 + 0] = i0; te[t * 2 + 1] = i1;
        tr[t * 2 + 0] = r0; tr[t * 2 + 1] = r1;
        tg[t * 2 + 0] = g0; tg[t * 2 + 1] = g1;
    }
}

__global__ void offs_kernel(const int* __restrict__ counts, int* __restrict__ offs) {
    if (threadIdx.x == 0 && blockIdx.x == 0) {
        int acc = 0;
        for (int e = 0; e < EE; e++) { offs[e] = acc; acc += counts[e]; }
        offs[EE] = acc;
    }
}

__global__ void pack_kernel(const int* __restrict__ te, const int* __restrict__ tr,
                            const int* __restrict__ offs,
                            int* __restrict__ pair, int* __restrict__ slot)
{
    int t = blockIdx.x * blockDim.x + threadIdx.x;
    if (t >= TT) return;
    #pragma unroll
    for (int k2 = 0; k2 < 2; k2++) {
        int e = te[t * 2 + k2];
        int s = offs[e] + tr[t * 2 + k2];
        pair[s] = t;
        slot[t * 2 + k2] = s;
    }
}

__global__ void combine_kernel(const int* __restrict__ slot,
                               const float* __restrict__ tg,
                               const float* __restrict__ ybuf,
                               float* __restrict__ out)
{
    int t = blockIdx.x, tid = threadIdx.x;
    int s0 = slot[t * 2], s1 = slot[t * 2 + 1];
    float g0 = tg[t * 2], g1 = tg[t * 2 + 1];
    const float4* y0 = reinterpret_cast<const float4*>(ybuf + (size_t)s0 * DD);
    const float4* y1 = reinterpret_cast<const float4*>(ybuf + (size_t)s1 * DD);
    float4* op = reinterpret_cast<float4*>(out + (size_t)t * DD);
    float4 a = op[tid], b0 = y0[tid], b1 = y1[tid];
    a.x += g0 * b0.x + g1 * b1.x;
    a.y += g0 * b0.y + g1 * b1.y;
    a.z += g0 * b0.z + g1 * b1.z;
    a.w += g0 * b0.w + g1 * b1.w;
    op[tid] = a;
}

// ---------------- launch ----------------
extern "C" void kernel_launch(void* const* d_in, const int* in_sizes, int n_in,
                              void* d_out, int out_size)
{
    const float* x      = (const float*)d_in[0];
    const float* deltas = (const float*)d_in[1];
    const float* ln1_s  = (const float*)d_in[2];
    const float* ln1_b  = (const float*)d_in[3];
    const float* wq     = (const float*)d_in[4];
    const float* bq     = (const float*)d_in[5];
    const float* wk     = (const float*)d_in[6];
    const float* bk     = (const float*)d_in[7];
    const float* wv     = (const float*)d_in[8];
    const float* bv     = (const float*)d_in[9];
    const float* wo     = (const float*)d_in[10];
    const float* bo     = (const float*)d_in[11];
    const float* tdcy   = (const float*)d_in[12];
    const float* ln2_s  = (const float*)d_in[13];
    const float* ln2_b  = (const float*)d_in[14];
    const float* rw     = (const float*)d_in[15];
    const float* rb     = (const float*)d_in[16];
    const float* w1     = (const float*)d_in[17];
    const float* b1     = (const float*)d_in[18];
    const float* w2     = (const float*)d_in[19];
    const float* b2     = (const float*)d_in[20];
    float* out = (float*)d_out;

    float *p_xn, *p_q, *p_k, *p_v, *p_o, *p_xn2, *p_xn2r, *p_h, *p_y, *p_tg;
    float *p_wqr, *p_wkr, *p_wvr, *p_wor;
    int *p_counts, *p_offs, *p_te, *p_tr, *p_pair, *p_slot;
    cudaGetSymbolAddress((void**)&p_xn,  g_xn);
    cudaGetSymbolAddress((void**)&p_q,   g_q);
    cudaGetSymbolAddress((void**)&p_k,   g_k);
    cudaGetSymbolAddress((void**)&p_v,   g_v);
    cudaGetSymbolAddress((void**)&p_o,   g_o);
    cudaGetSymbolAddress((void**)&p_xn2, g_xn2);
    cudaGetSymbolAddress((void**)&p_xn2r, g_xn2r);
    cudaGetSymbolAddress((void**)&p_h,   g_h);
    cudaGetSymbolAddress((void**)&p_y,   g_y);
    cudaGetSymbolAddress((void**)&p_wqr, g_wqr);
    cudaGetSymbolAddress((void**)&p_wkr, g_wkr);
    cudaGetSymbolAddress((void**)&p_wvr, g_wvr);
    cudaGetSymbolAddress((void**)&p_wor, g_wor);
    cudaGetSymbolAddress((void**)&p_counts, g_counts);
    cudaGetSymbolAddress((void**)&p_offs,   g_offs);
    cudaGetSymbolAddress((void**)&p_te,     g_te);
    cudaGetSymbolAddress((void**)&p_tr,     g_tr);
    cudaGetSymbolAddress((void**)&p_tg,     g_tg);
    cudaGetSymbolAddress((void**)&p_pair,   g_pair);
    cudaGetSymbolAddress((void**)&p_slot,   g_slot);

    const int GEMM_SMEM = GEMM_SMEM_FLOATS * (int)sizeof(float);
    const int ATTN_SMEM = ATTN_SMEM_FLOATS * (int)sizeof(float);
    static bool attr_done = false;
    if (!attr_done) {
        cudaFuncSetAttribute(gemm_tc<0, false, false, false, true,  true,  false>,
                             cudaFuncAttributeMaxDynamicSharedMemorySize, GEMM_SMEM);
        cudaFuncSetAttribute(gemm_tc<0, true,  false, false, false, false, false>,
                             cudaFuncAttributeMaxDynamicSharedMemorySize, GEMM_SMEM);
        cudaFuncSetAttribute(gemm_tc<1, false, true,  true,  false, true,  true >,
                             cudaFuncAttributeMaxDynamicSharedMemorySize, GEMM_SMEM);
        cudaFuncSetAttribute(gemm_tc<0, false, false, true,  false, false, true >,
                             cudaFuncAttributeMaxDynamicSharedMemorySize, GEMM_SMEM);
        cudaFuncSetAttribute(attn_tc,
                             cudaFuncAttributeMaxDynamicSharedMemorySize, ATTN_SMEM);
        attr_done = true;
    }

    // 0) pre-round small weights only (w1/w2 are rounded in-fragment)
    f2tf_kernel<<<(DD * DD / 4 + 255) / 256, 256>>>(wq, p_wqr, DD * DD / 4);
    f2tf_kernel<<<(DD * GG * HDIM / 4 + 255) / 256, 256>>>(wk, p_wkr, DD * GG * HDIM / 4);
    f2tf_kernel<<<(DD * GG * HDIM / 4 + 255) / 256, 256>>>(wv, p_wvr, DD * GG * HDIM / 4);
    f2tf_kernel<<<(DD * DD / 4 + 255) / 256, 256>>>(wo, p_wor, DD * DD / 4);
    // 1) LN1 (rounded output: feeds QKV GEMM only)
    ln_kernel<true><<<TT, 256>>>(x, ln1_s, ln1_b, p_xn);
    // 2) fused Q/K/V projection (outputs rounded for attention MMA)
    gemm_tc<0, false, false, false, true, true, false><<<dim3(12, TT / BM, 1), 256, GEMM_SMEM>>>(
        p_xn, p_wqr, bq, nullptr, p_q, TT, DD, DD, nullptr, nullptr, nullptr, 0, 0,
        p_wkr, bk, p_k, p_wvr, bv, p_v);
    // 3) attention (output rounded for O-proj)
    attn_tc<<<dim3(SS / 64, HH, BB), 256, ATTN_SMEM>>>(p_q, p_k, p_v, deltas, tdcy, p_o);
    // 4) output projection + residual (exact out)
    gemm_tc<0, true, false, false, false, false, false><<<dim3(DD / BN, TT / BM, 1), 256, GEMM_SMEM>>>(
        p_o, p_wor, bo, x, out, TT, DD, DD, nullptr, nullptr, nullptr, 0, 0,
        nullptr, nullptr, nullptr, nullptr, nullptr, nullptr);
    // 5) LN2 exact (router) + rounded copy (GEMM1 A)
    ln_kernel<false><<<TT, 256>>>(out, ln2_s, ln2_b, p_xn2);
    f2tf_kernel<<<(TT * DD / 4 + 255) / 256, 256>>>(p_xn2, p_xn2r, TT * DD / 4);
    // 6) router + bucketing
    zero_kernel<<<1, 32>>>(p_counts);
    router_kernel<<<TT, 256>>>(p_xn2, rw, rb, p_counts, p_te, p_tr, p_tg);
    offs_kernel<<<1, 1>>>(p_counts, p_offs);
    pack_kernel<<<TT / 256, 256>>>(p_te, p_tr, p_offs, p_pair, p_slot);
    // 7) expert GEMM1 (gathered, gelu, rounded h out; B=w1 raw with in-frag CVT)
    gemm_tc<1, false, true, true, false, true, true><<<dim3(FF / BN, NPAIR / BM, EE), 256, GEMM_SMEM>>>(
        p_xn2r, w1, b1, nullptr, p_h, 0, FF, DD, p_pair, p_counts, p_offs,
        (size_t)DD * FF, (size_t)FF,
        nullptr, nullptr, nullptr, nullptr, nullptr, nullptr);
    // 8) expert GEMM2 (exact y out; B=w2 raw with in-frag CVT)
    gemm_tc<0, false, false, true, false, false, true><<<dim3(DD / BN, NPAIR / BM, EE), 256, GEMM_SMEM>>>(
        p_h, w2, b2, nullptr, p_y, 0, DD, FF, nullptr, p_counts, p_offs,
        (size_t)FF * DD, (size_t)DD,
        nullptr, nullptr, nullptr, nullptr, nullptr, nullptr);
    // 9) combine
    combine_kernel<<<TT, 256>>>(p_slot, p_tg, p_y, out);

    (void)in_sizes; (void)n_in; (void)out_size;
}

// round 13
// speedup vs baseline: 1.0782x; 1.0105x over previous
#include <cuda_runtime.h>
#include <cstdint>
#include <math.h>
#include <mma.h>

using namespace nvcuda;

// ---------------- problem constants ----------------
#define BB   2
#define SS   2048
#define TT   4096          // B*S tokens
#define DD   1024
#define HH   16
#define GG   4
#define HDIM 64
#define EE   8
#define FF   4096
#define NPAIR (TT*2)

// ---------------- scratch ----------------
__device__ float g_xn [TT*DD];           // tf32-rounded
__device__ float g_q  [TT*DD];           // tf32-rounded
__device__ float g_k  [TT*GG*HDIM];      // tf32-rounded
__device__ float g_v  [TT*GG*HDIM];      // tf32-rounded
__device__ float g_o  [TT*DD];           // tf32-rounded
__device__ float g_xn2 [TT*DD];          // exact (router)
__device__ float g_xn2r[TT*DD];          // tf32-rounded (GEMM1 A)
__device__ float g_h  [(size_t)NPAIR*FF];   // tf32-rounded (gelu out)
__device__ float g_y  [(size_t)NPAIR*DD];   // exact
__device__ float g_wqr[DD*DD];
__device__ float g_wkr[DD*GG*HDIM];
__device__ float g_wvr[DD*GG*HDIM];
__device__ float g_wor[DD*DD];
__device__ int   g_counts[EE];
__device__ int   g_offs[EE+1];
__device__ int   g_te [NPAIR];
__device__ int   g_tr [NPAIR];
__device__ float g_tg [NPAIR];
__device__ int   g_pair[NPAIR];
__device__ int   g_slot[NPAIR];

// ---------------- helpers ----------------
__device__ __forceinline__ float gelu_tanh(float x) {
    const float c0 = 0.7978845608028654f;
    float x3 = x * x * x;
    float t = tanhf(c0 * (x + 0.044715f * x3));
    return 0.5f * x * (1.0f + t);
}

template<class Frag>
__device__ __forceinline__ void frag_to_tf32(Frag& f) {
    #pragma unroll
    for (int i = 0; i < f.num_elements; i++)
        f.x[i] = wmma::__float_to_tf32(f.x[i]);
}

__device__ __forceinline__ void cp16(void* s, const void* g) {
    unsigned int sa = (unsigned int)__cvta_generic_to_shared(s);
    asm volatile("cp.async.cg.shared.global [%0], [%1], 16;\n" :: "r"(sa), "l"(g));
}
__device__ __forceinline__ void cp16z(void* s, const void* g, bool v) {
    unsigned int sa = (unsigned int)__cvta_generic_to_shared(s);
    int sz = v ? 16 : 0;
    asm volatile("cp.async.cg.shared.global [%0], [%1], 16, %2;\n" :: "r"(sa), "l"(g), "r"(sz));
}
__device__ __forceinline__ void cp_commit() { asm volatile("cp.async.commit_group;\n"); }
template<int N> __device__ __forceinline__ void cp_wait() {
    asm volatile("cp.async.wait_group %0;\n" :: "n"(N));
}

// ---------------- fp32 -> tf32(RN) rounding pass ----------------
__global__ void f2tf_kernel(const float* __restrict__ in,
                            float* __restrict__ out, int n4)
{
    int i = blockIdx.x * blockDim.x + threadIdx.x;
    if (i >= n4) return;
    float4 v = reinterpret_cast<const float4*>(in)[i];
    v.x = wmma::__float_to_tf32(v.x);
    v.y = wmma::__float_to_tf32(v.y);
    v.z = wmma::__float_to_tf32(v.z);
    v.w = wmma::__float_to_tf32(v.w);
    reinterpret_cast<float4*>(out)[i] = v;
}

// ---------------- LayerNorm. MODE: 0=exact, 1=rounded, 2=dual (exact + rounded copy) ----------------
template<int MODE>
__global__ void ln_kernel(const float* __restrict__ x,
                          const float* __restrict__ scale,
                          const float* __restrict__ bias,
                          float* __restrict__ out,
                          float* __restrict__ outr)
{
    __shared__ float red[8];
    int t = blockIdx.x, tid = threadIdx.x;
    const float4* xp = reinterpret_cast<const float4*>(x + (size_t)t * DD);
    float4 v = xp[tid];
    float s = v.x + v.y + v.z + v.w;
    #pragma unroll
    for (int o = 16; o; o >>= 1) s += __shfl_xor_sync(0xffffffffu, s, o);
    if ((tid & 31) == 0) red[tid >> 5] = s;
    __syncthreads();
    if (tid < 8) {
        float r = red[tid];
        #pragma unroll
        for (int o = 4; o; o >>= 1) r += __shfl_xor_sync(0xffu, r, o);
        if (tid == 0) red[0] = r;
    }
    __syncthreads();
    float mu = red[0] * (1.0f / DD);
    float d0 = v.x - mu, d1 = v.y - mu, d2 = v.z - mu, d3 = v.w - mu;
    float sq = d0*d0 + d1*d1 + d2*d2 + d3*d3;
    #pragma unroll
    for (int o = 16; o; o >>= 1) sq += __shfl_xor_sync(0xffffffffu, sq, o);
    __syncthreads();
    if ((tid & 31) == 0) red[tid >> 5] = sq;
    __syncthreads();
    if (tid < 8) {
        float r = red[tid];
        #pragma unroll
        for (int o = 4; o; o >>= 1) r += __shfl_xor_sync(0xffu, r, o);
        if (tid == 0) red[0] = r;
    }
    __syncthreads();
    float rstd = rsqrtf(red[0] * (1.0f / DD) + 1e-6f);
    float4 sc = reinterpret_cast<const float4*>(scale)[tid];
    float4 bi = reinterpret_cast<const float4*>(bias)[tid];
    float4 o4;
    o4.x = d0 * rstd * sc.x + bi.x;
    o4.y = d1 * rstd * sc.y + bi.y;
    o4.z = d2 * rstd * sc.z + bi.z;
    o4.w = d3 * rstd * sc.w + bi.w;
    if (MODE == 1) {
        o4.x = wmma::__float_to_tf32(o4.x);
        o4.y = wmma::__float_to_tf32(o4.y);
        o4.z = wmma::__float_to_tf32(o4.z);
        o4.w = wmma::__float_to_tf32(o4.w);
    }
    reinterpret_cast<float4*>(out + (size_t)t * DD)[tid] = o4;
    if (MODE == 2) {
        float4 r4;
        r4.x = wmma::__float_to_tf32(o4.x);
        r4.y = wmma::__float_to_tf32(o4.y);
        r4.z = wmma::__float_to_tf32(o4.z);
        r4.w = wmma::__float_to_tf32(o4.w);
        reinterpret_cast<float4*>(outr + (size_t)t * DD)[tid] = r4;
    }
}

// ---------------- tf32 GEMM, cp.async double-buffered, 128x128x32 (champion config) ----------------
// A operands MUST be pre-rounded to tf32 (RN). B: pre-rounded unless CVTB (in-frag RN).
#define BM 128
#define BN 128
#define BKT 32
#define ALD 40
#define BLD 136
#define GEMM_SMEM_FLOATS (2*128*ALD + 2*32*BLD + 8*256)

template<int ACT, bool RESID, bool GATHER, bool SEG, bool QKV, bool ROUT, bool CVTB>
__global__ __launch_bounds__(256, 2)
void gemm_tc(const float* __restrict__ A,
             const float* __restrict__ Bmat,
             const float* __restrict__ biasp,
             const float* __restrict__ resid,
             float* __restrict__ C,
             int M, int N, int Kd,
             const int* __restrict__ gather,
             const int* __restrict__ counts,
             const int* __restrict__ offs,
             size_t strideB, size_t strideBias,
             const float* __restrict__ B2, const float* __restrict__ bias2, float* __restrict__ C2,
             const float* __restrict__ B3, const float* __restrict__ bias3, float* __restrict__ C3)
{
    extern __shared__ float smem[];
    float* As    = smem;                       // [2][128][ALD]
    float* Bs    = As + 2 * 128 * ALD;         // [2][32][BLD]
    float* stage = Bs + 2 * 32 * BLD;          // [8][256]

    int off = 0, Mseg = M, Nn = N, bn;
    const float* Bm = Bmat;
    const float* bias = biasp;
    float* Cout = C;
    if (QKV) {
        int xb = blockIdx.x;
        if (xb < 8)       { bn = xb * 128; }
        else if (xb < 10) { Bm = B2; bias = bias2; Cout = C2; Nn = 256; bn = (xb - 8) * 128; }
        else              { Bm = B3; bias = bias3; Cout = C3; Nn = 256; bn = (xb - 10) * 128; }
    } else {
        bn = blockIdx.x * BN;
    }
    if (SEG) {
        int e = blockIdx.z;
        Mseg = counts[e];
        off  = offs[e];
        Bm   = Bmat + (size_t)e * strideB;
        bias = biasp + (size_t)e * strideBias;
    }
    int bm = blockIdx.y * BM;
    if (bm >= Mseg) return;

    int tid  = threadIdx.x;
    int wid  = tid >> 5;
    int lane = tid & 31;
    int wm   = wid & 3;
    int wn   = wid >> 2;

    int arow = tid >> 3;            // 0..31
    int acol = (tid & 7) * 4;       // 0..28
    const float* aptr[4];
    bool aok[4];
    #pragma unroll
    for (int p = 0; p < 4; p++) {
        int grow = bm + arow + p * 32;
        aok[p] = grow < Mseg;
        long src = 0;
        if (aok[p]) src = GATHER ? (long)gather[off + grow] : (long)(off + grow);
        aptr[p] = A + (size_t)src * Kd + acol;
    }
    int brow = tid >> 3;
    int bcol = (tid & 7) * 4;
    const float* bptr = Bm + (size_t)brow * Nn + bn + bcol;

    wmma::fragment<wmma::accumulator, 16, 16, 8, float> acc[2][4];
    #pragma unroll
    for (int i = 0; i < 2; i++)
        #pragma unroll
        for (int j = 0; j < 4; j++) wmma::fill_fragment(acc[i][j], 0.0f);

    int nk = Kd / BKT;

    {
        #pragma unroll
        for (int p = 0; p < 4; p++)
            cp16z(&As[(0 * 128 + arow + p * 32) * ALD + acol], aptr[p], aok[p]);
        #pragma unroll
        for (int p = 0; p < 4; p++)
            cp16(&Bs[(0 * 32 + brow) * BLD + bcol + p * 32], bptr + p * 32);
        cp_commit();
    }

    for (int it = 0; it < nk; it++) {
        int buf = it & 1;
        if (it + 1 < nk) {
            int k0 = (it + 1) * BKT;
            int nb = buf ^ 1;
            #pragma unroll
            for (int p = 0; p < 4; p++)
                cp16z(&As[(nb * 128 + arow + p * 32) * ALD + acol], aptr[p] + k0, aok[p]);
            #pragma unroll
            for (int p = 0; p < 4; p++)
                cp16(&Bs[(nb * 32 + brow) * BLD + bcol + p * 32],
                     bptr + (size_t)k0 * Nn + p * 32);
        }
        cp_commit();
        cp_wait<1>();
        __syncthreads();

        #pragma unroll
        for (int kk = 0; kk < BKT / 8; kk++) {
            wmma::fragment<wmma::matrix_a, 16, 16, 8, wmma::precision::tf32, wmma::row_major> af[2];
            wmma::fragment<wmma::matrix_b, 16, 16, 8, wmma::precision::tf32, wmma::row_major> bf[4];
            #pragma unroll
            for (int i = 0; i < 2; i++)
                wmma::load_matrix_sync(af[i], &As[(buf * 128 + wm * 32 + i * 16) * ALD + kk * 8], ALD);
            #pragma unroll
            for (int j = 0; j < 4; j++) {
                wmma::load_matrix_sync(bf[j], &Bs[(buf * 32 + kk * 8) * BLD + wn * 64 + j * 16], BLD);
                if (CVTB) frag_to_tf32(bf[j]);
            }
            #pragma unroll
            for (int i = 0; i < 2; i++)
                #pragma unroll
                for (int j = 0; j < 4; j++)
                    wmma::mma_sync(acc[i][j], af[i], bf[j], acc[i][j]);
        }
        __syncthreads();
    }

    int er  = lane >> 1;
    int ec0 = (lane & 1) * 8;
    #pragma unroll
    for (int i = 0; i < 2; i++) {
        #pragma unroll
        for (int j = 0; j < 4; j++) {
            wmma::store_matrix_sync(&stage[wid * 256], acc[i][j], 16, wmma::mem_row_major);
            __syncwarp();
            int grow = bm + wm * 32 + i * 16 + er;
            if (grow < Mseg) {
                int gcol = bn + wn * 64 + j * 16 + ec0;
                size_t cidx = (size_t)(off + grow) * Nn + gcol;
                float v[8];
                #pragma unroll
                for (int q = 0; q < 4; q++) {
                    v[q]     = stage[wid * 256 + er * 16 + ec0 + q]     + bias[gcol + q];
                    v[q + 4] = stage[wid * 256 + er * 16 + ec0 + 4 + q] + bias[gcol + 4 + q];
                }
                if (ACT == 1) {
                    #pragma unroll
                    for (int q = 0; q < 8; q++) v[q] = gelu_tanh(v[q]);
                }
                if (RESID) {
                    float4 r0 = *reinterpret_cast<const float4*>(&resid[cidx]);
                    float4 r1 = *reinterpret_cast<const float4*>(&resid[cidx + 4]);
                    v[0] += r0.x; v[1] += r0.y; v[2] += r0.z; v[3] += r0.w;
                    v[4] += r1.x; v[5] += r1.y; v[6] += r1.z; v[7] += r1.w;
                }
                if (ROUT) {
                    #pragma unroll
                    for (int q = 0; q < 8; q++) v[q] = wmma::__float_to_tf32(v[q]);
                }
                *reinterpret_cast<float4*>(&Cout[cidx])     = make_float4(v[0], v[1], v[2], v[3]);
                *reinterpret_cast<float4*>(&Cout[cidx + 4]) = make_float4(v[4], v[5], v[6], v[7]);
            }
            __syncwarp();
        }
    }
}

// ---------------- attention: tf32 wmma flash, 64q x 64k, K/V prefetch overlap ----------------
// q/k/v pre-rounded. V double-buffered; K single buffer prefetched after S phase.
// 3 barriers per kt-iteration (hazards documented inline).
#define APD 68
#define ATTN_SMEM_FLOATS (6*64*APD + 3*64)

__global__ __launch_bounds__(256, 2)
void attn_tc(const float* __restrict__ qb,
             const float* __restrict__ kb,
             const float* __restrict__ vb,
             const float* __restrict__ deltas,
             const float* __restrict__ time_decay,
             float* __restrict__ ob)
{
    extern __shared__ float sm[];
    float* qs  = sm;
    float* ks  = qs  + 64 * APD;
    float* vs  = ks  + 64 * APD;          // 2 buffers: vs + vbuf*64*APD
    float* ps  = vs  + 2 * 64 * APD;
    float* os  = ps  + 64 * APD;
    float* dq_s = os + 64 * APD;
    float* dk_s = dq_s + 64;
    float* l_s  = dk_s + 64;

    int qt = blockIdx.x, h = blockIdx.y, b = blockIdx.z;
    int g = h >> 2;
    int tid = threadIdx.x;
    int wid = tid >> 5;
    float td = time_decay[h];
    float lam = (td > 20.f) ? td : log1pf(__expf(td));
    int q0 = qt * 64;

    // prologue: load Q + K[0] + V[0] (buf 0)
    {
        #pragma unroll
        for (int p = 0; p < 4; p++) {
            int ch = tid + p * 256;
            int r = ch >> 4, cc = (ch & 15) * 4;
            cp16(&qs[r * APD + cc],
                 qb + ((size_t)(b * SS + q0 + r)) * DD + h * HDIM + cc);
            size_t base = ((size_t)(b * SS + r)) * (GG * HDIM) + g * HDIM + cc;
            cp16(&ks[r * APD + cc], kb + base);
            cp16(&vs[r * APD + cc], vb + base);
        }
        cp_commit();
    }
    if (tid < 64) dq_s[tid] = deltas[b * SS + q0 + tid];
    #pragma unroll
    for (int p = 0; p < 16; p++) {
        int idx = tid + p * 256;
        os[(idx >> 6) * APD + (idx & 63)] = 0.f;
    }

    const float scale = 0.125f;
    int rw = wid & 3;
    int cw = wid >> 2;
    int prow = tid >> 2, psub = tid & 3;
    float m_prev = -INFINITY, l_run = 0.f;
    const int NT = SS / 64;

    for (int kt = 0; kt < NT; kt++) {
        int vbuf = kt & 1;
        // dk for THIS kt. Safe: previous softmax (last dk reader) is before
        // previous after-softmax barrier, which precedes this point.
        if (tid < 64) dk_s[tid] = deltas[b * SS + kt * 64 + tid];
        cp_wait<0>();       // ks[kt], vs[kt] (and q on kt=0) complete per-thread
        __syncthreads();    // cross-thread visibility (also orders dk_s store)

        // S = Q @ K^T
        {
            wmma::fragment<wmma::accumulator, 16, 16, 8, float> sacc[2];
            wmma::fill_fragment(sacc[0], 0.f);
            wmma::fill_fragment(sacc[1], 0.f);
            #pragma unroll
            for (int kk = 0; kk < 8; kk++) {
                wmma::fragment<wmma::matrix_a, 16, 16, 8, wmma::precision::tf32, wmma::row_major> af;
                wmma::fragment<wmma::matrix_b, 16, 16, 8, wmma::precision::tf32, wmma::col_major> bf[2];
                wmma::load_matrix_sync(af, &qs[(rw * 16) * APD + kk * 8], APD);
                #pragma unroll
                for (int j = 0; j < 2; j++)
                    wmma::load_matrix_sync(bf[j], &ks[(cw * 32 + j * 16) * APD + kk * 8], APD);
                #pragma unroll
                for (int j = 0; j < 2; j++)
                    wmma::mma_sync(sacc[j], af, bf[j], sacc[j]);
            }
            #pragma unroll
            for (int j = 0; j < 2; j++)
                wmma::store_matrix_sync(&ps[(rw * 16) * APD + cw * 32 + j * 16],
                                        sacc[j], APD, wmma::mem_row_major);
        }
        __syncthreads();    // ks fully consumed; ps visible to softmax threads

        // prefetch K[kt+1] into ks (now free) and V[kt+1] into the other V buffer;
        // overlaps softmax + PV below.
        if (kt + 1 < NT) {
            #pragma unroll
            for (int p = 0; p < 4; p++) {
                int ch = tid + p * 256;
                int r = ch >> 4, cc = (ch & 15) * 4;
                size_t base = ((size_t)(b * SS + (kt + 1) * 64 + r)) * (GG * HDIM) + g * HDIM + cc;
                cp16(&ks[r * APD + cc], kb + base);
                cp16(&vs[(vbuf ^ 1) * 64 * APD + r * APD + cc], vb + base);
            }
        }
        cp_commit();

        // softmax + alpha-scale of os rows (thread owns row prow, cols psub*16..+15)
        {
            float dqv = dq_s[prow];
            float sv[16];
            float mt = -INFINITY;
            #pragma unroll
            for (int j = 0; j < 16; j++) {
                int c = psub * 16 + j;
                float s = ps[prow * APD + c] * scale - lam * fabsf(dqv - dk_s[c]);
                sv[j] = s;
                mt = fmaxf(mt, s);
            }
            mt = fmaxf(mt, __shfl_xor_sync(0xffffffffu, mt, 1));
            mt = fmaxf(mt, __shfl_xor_sync(0xffffffffu, mt, 2));
            float m_new = fmaxf(m_prev, mt);
            float alpha = __expf(m_prev - m_new);
            float sum = 0.f;
            #pragma unroll
            for (int j = 0; j < 16; j++) {
                float p = __expf(sv[j] - m_new);
                ps[prow * APD + psub * 16 + j] = p;
                sum += p;
            }
            sum += __shfl_xor_sync(0xffffffffu, sum, 1);
            sum += __shfl_xor_sync(0xffffffffu, sum, 2);
            l_run = l_run * alpha + sum;
            m_prev = m_new;
            #pragma unroll
            for (int j = 0; j < 16; j++)
                os[prow * APD + psub * 16 + j] *= alpha;
        }
        __syncthreads();    // ps(updated) + scaled os visible to PV warps

        // os += P @ V[vbuf]  (accumulator lives in os; writes vs[vbuf^1] in flight
        // touch the OTHER buffer — no conflict). No trailing barrier: next
        // iteration's top wait+sync orders this mma before any ks/vs reuse.
        {
            wmma::fragment<wmma::accumulator, 16, 16, 8, float> pacc[2];
            #pragma unroll
            for (int j = 0; j < 2; j++)
                wmma::load_matrix_sync(pacc[j], &os[(rw * 16) * APD + cw * 32 + j * 16],
                                       APD, wmma::mem_row_major);
            #pragma unroll
            for (int kk = 0; kk < 8; kk++) {
                wmma::fragment<wmma::matrix_a, 16, 16, 8, wmma::precision::tf32, wmma::row_major> af;
                wmma::fragment<wmma::matrix_b, 16, 16, 8, wmma::precision::tf32, wmma::row_major> bf[2];
                wmma::load_matrix_sync(af, &ps[(rw * 16) * APD + kk * 8], APD);
                frag_to_tf32(af);   // P is fresh fp32 -> RN round
                #pragma unroll
                for (int j = 0; j < 2; j++)
                    wmma::load_matrix_sync(bf[j], &vs[vbuf * 64 * APD + (kk * 8) * APD + cw * 32 + j * 16], APD);
                #pragma unroll
                for (int j = 0; j < 2; j++)
                    wmma::mma_sync(pacc[j], af, bf[j], pacc[j]);
            }
            #pragma unroll
            for (int j = 0; j < 2; j++)
                wmma::store_matrix_sync(&os[(rw * 16) * APD + cw * 32 + j * 16],
                                        pacc[j], APD, wmma::mem_row_major);
        }
    }
    __syncthreads();        // final PV done before reading os below
    if (psub == 0) l_s[prow] = l_run;
    __syncthreads();
    #pragma unroll
    for (int p = 0; p < 16; p++) {
        int idx = tid + p * 256;
        int r = idx >> 6, c = idx & 63;
        ob[((size_t)(b * SS + q0 + r)) * DD + h * HDIM + c] =
            wmma::__float_to_tf32(os[r * APD + c] / l_s[r]);
    }
}

// ---------------- router + bucketing ----------------
__global__ void zero_kernel(int* counts) {
    if (threadIdx.x < EE) counts[threadIdx.x] = 0;
}

__global__ void router_kernel(const float* __restrict__ xn2,
                              const float* __restrict__ rw,
                              const float* __restrict__ rb,
                              int* __restrict__ counts,
                              int* __restrict__ te,
                              int* __restrict__ tr,
                              float* __restrict__ tg)
{
    __shared__ float lg[EE];
    int t = blockIdx.x, tid = threadIdx.x;
    int w = tid >> 5, lane = tid & 31;
    const float* xr = xn2 + (size_t)t * DD;
    float p = 0.f;
    for (int d = lane; d < DD; d += 32)
        p += xr[d] * rw[d * EE + w];
    #pragma unroll
    for (int o = 16; o; o >>= 1) p += __shfl_xor_sync(0xffffffffu, p, o);
    if (lane == 0) lg[w] = p + rb[w];
    __syncthreads();
    if (tid == 0) {
        float best = -INFINITY, second = -INFINITY;
        int i0 = 0, i1 = 0;
        #pragma unroll
        for (int e = 0; e < EE; e++) {
            float v = lg[e];
            if (v > best)        { second = best; i1 = i0; best = v; i0 = e; }
            else if (v > second) { second = v; i1 = e; }
        }
        float g0 = 1.0f / (1.0f + expf(second - best));
        float g1 = 1.0f - g0;
        int r0 = atomicAdd(&counts[i0], 1);
        int r1 = atomicAdd(&counts[i1], 1);
        te[t * 2 + 0] = i0; te[t * 2 + 1] = i1;
        tr[t * 2 + 0] = r0; tr[t * 2 + 1] = r1;
        tg[t * 2 + 0] = g0; tg[t * 2 + 1] = g1;
    }
}

__global__ void offs_kernel(const int* __restrict__ counts, int* __restrict__ offs) {
    if (threadIdx.x == 0 && blockIdx.x == 0) {
        int acc = 0;
        for (int e = 0; e < EE; e++) { offs[e] = acc; acc += counts[e]; }
        offs[EE] = acc;
    }
}

__global__ void pack_kernel(const int* __restrict__ te, const int* __restrict__ tr,
                            const int* __restrict__ offs,
                            int* __restrict__ pair, int* __restrict__ slot)
{
    int t = blockIdx.x * blockDim.x + threadIdx.x;
    if (t >= TT) return;
    #pragma unroll
    for (int k2 = 0; k2 < 2; k2++) {
        int e = te[t * 2 + k2];
        int s = offs[e] + tr[t * 2 + k2];
        pair[s] = t;
        slot[t * 2 + k2] = s;
    }
}

__global__ void combine_kernel(const int* __restrict__ slot,
                               const float* __restrict__ tg,
                               const float* __restrict__ ybuf,
                               float* __restrict__ out)
{
    int t = blockIdx.x, tid = threadIdx.x;
    int s0 = slot[t * 2], s1 = slot[t * 2 + 1];
    float g0 = tg[t * 2], g1 = tg[t * 2 + 1];
    const float4* y0 = reinterpret_cast<const float4*>(ybuf + (size_t)s0 * DD);
    const float4* y1 = reinterpret_cast<const float4*>(ybuf + (size_t)s1 * DD);
    float4* op = reinterpret_cast<float4*>(out + (size_t)t * DD);
    float4 a = op[tid], b0 = y0[tid], b1 = y1[tid];
    a.x += g0 * b0.x + g1 * b1.x;
    a.y += g0 * b0.y + g1 * b1.y;
    a.z += g0 * b0.z + g1 * b1.z;
    a.w += g0 * b0.w + g1 * b1.w;
    op[tid] = a;
}

// ---------------- launch ----------------
extern "C" void kernel_launch(void* const* d_in, const int* in_sizes, int n_in,
                              void* d_out, int out_size)
{
    const float* x      = (const float*)d_in[0];
    const float* deltas = (const float*)d_in[1];
    const float* ln1_s  = (const float*)d_in[2];
    const float* ln1_b  = (const float*)d_in[3];
    const float* wq     = (const float*)d_in[4];
    const float* bq     = (const float*)d_in[5];
    const float* wk     = (const float*)d_in[6];
    const float* bk     = (const float*)d_in[7];
    const float* wv     = (const float*)d_in[8];
    const float* bv     = (const float*)d_in[9];
    const float* wo     = (const float*)d_in[10];
    const float* bo     = (const float*)d_in[11];
    const float* tdcy   = (const float*)d_in[12];
    const float* ln2_s  = (const float*)d_in[13];
    const float* ln2_b  = (const float*)d_in[14];
    const float* rw     = (const float*)d_in[15];
    const float* rb     = (const float*)d_in[16];
    const float* w1     = (const float*)d_in[17];
    const float* b1     = (const float*)d_in[18];
    const float* w2     = (const float*)d_in[19];
    const float* b2     = (const float*)d_in[20];
    float* out = (float*)d_out;

    float *p_xn, *p_q, *p_k, *p_v, *p_o, *p_xn2, *p_xn2r, *p_h, *p_y, *p_tg;
    float *p_wqr, *p_wkr, *p_wvr, *p_wor;
    int *p_counts, *p_offs, *p_te, *p_tr, *p_pair, *p_slot;
    cudaGetSymbolAddress((void**)&p_xn,  g_xn);
    cudaGetSymbolAddress((void**)&p_q,   g_q);
    cudaGetSymbolAddress((void**)&p_k,   g_k);
    cudaGetSymbolAddress((void**)&p_v,   g_v);
    cudaGetSymbolAddress((void**)&p_o,   g_o);
    cudaGetSymbolAddress((void**)&p_xn2, g_xn2);
    cudaGetSymbolAddress((void**)&p_xn2r, g_xn2r);
    cudaGetSymbolAddress((void**)&p_h,   g_h);
    cudaGetSymbolAddress((void**)&p_y,   g_y);
    cudaGetSymbolAddress((void**)&p_wqr, g_wqr);
    cudaGetSymbolAddress((void**)&p_wkr, g_wkr);
    cudaGetSymbolAddress((void**)&p_wvr, g_wvr);
    cudaGetSymbolAddress((void**)&p_wor, g_wor);
    cudaGetSymbolAddress((void**)&p_counts, g_counts);
    cudaGetSymbolAddress((void**)&p_offs,   g_offs);
    cudaGetSymbolAddress((void**)&p_te,     g_te);
    cudaGetSymbolAddress((void**)&p_tr,     g_tr);
    cudaGetSymbolAddress((void**)&p_tg,     g_tg);
    cudaGetSymbolAddress((void**)&p_pair,   g_pair);
    cudaGetSymbolAddress((void**)&p_slot,   g_slot);

    const int GEMM_SMEM = GEMM_SMEM_FLOATS * (int)sizeof(float);
    const int ATTN_SMEM = ATTN_SMEM_FLOATS * (int)sizeof(float);
    static bool attr_done = false;
    if (!attr_done) {
        cudaFuncSetAttribute(gemm_tc<0, false, false, false, true,  true,  false>,
                             cudaFuncAttributeMaxDynamicSharedMemorySize, GEMM_SMEM);
        cudaFuncSetAttribute(gemm_tc<0, true,  false, false, false, false, false>,
                             cudaFuncAttributeMaxDynamicSharedMemorySize, GEMM_SMEM);
        cudaFuncSetAttribute(gemm_tc<1, false, true,  true,  false, true,  true >,
                             cudaFuncAttributeMaxDynamicSharedMemorySize, GEMM_SMEM);
        cudaFuncSetAttribute(gemm_tc<0, false, false, true,  false, false, true >,
                             cudaFuncAttributeMaxDynamicSharedMemorySize, GEMM_SMEM);
        cudaFuncSetAttribute(attn_tc,
                             cudaFuncAttributeMaxDynamicSharedMemorySize, ATTN_SMEM);
        attr_done = true;
    }

    // launch order arranged so QKV GEMM is launch index 5 (ncu -s 5 -c 1 profiles it)
    // 0) LN1 (rounded output: feeds QKV GEMM only)
    ln_kernel<1><<<TT, 256>>>(x, ln1_s, ln1_b, p_xn, nullptr);
    // 1-4) pre-round small weights (w1/w2 are rounded in-fragment)
    f2tf_kernel<<<(DD * DD / 4 + 255) / 256, 256>>>(wq, p_wqr, DD * DD / 4);
    f2tf_kernel<<<(DD * GG * HDIM / 4 + 255) / 256, 256>>>(wk, p_wkr, DD * GG * HDIM / 4);
    f2tf_kernel<<<(DD * GG * HDIM / 4 + 255) / 256, 256>>>(wv, p_wvr, DD * GG * HDIM / 4);
    f2tf_kernel<<<(DD * DD / 4 + 255) / 256, 256>>>(wo, p_wor, DD * DD / 4);
    // 5) fused Q/K/V projection (outputs rounded for attention MMA)
    gemm_tc<0, false, false, false, true, true, false><<<dim3(12, TT / BM, 1), 256, GEMM_SMEM>>>(
        p_xn, p_wqr, bq, nullptr, p_q, TT, DD, DD, nullptr, nullptr, nullptr, 0, 0,
        p_wkr, bk, p_k, p_wvr, bv, p_v);
    // 6) attention (output rounded for O-proj)
    attn_tc<<<dim3(SS / 64, HH, BB), 256, ATTN_SMEM>>>(p_q, p_k, p_v, deltas, tdcy, p_o);
    // 7) output projection + residual (exact out)
    gemm_tc<0, true, false, false, false, false, false><<<dim3(DD / BN, TT / BM, 1), 256, GEMM_SMEM>>>(
        p_o, p_wor, bo, x, out, TT, DD, DD, nullptr, nullptr, nullptr, 0, 0,
        nullptr, nullptr, nullptr, nullptr, nullptr, nullptr);
    // 8) LN2 dual: exact (router) + rounded (GEMM1 A) in one pass
    ln_kernel<2><<<TT, 256>>>(out, ln2_s, ln2_b, p_xn2, p_xn2r);
    // 9) router + bucketing
    zero_kernel<<<1, 32>>>(p_counts);
    router_kernel<<<TT, 256>>>(p_xn2, rw, rb, p_counts, p_te, p_tr, p_tg);
    offs_kernel<<<1, 1>>>(p_counts, p_offs);
    pack_kernel<<<TT / 256, 256>>>(p_te, p_tr, p_offs, p_pair, p_slot);
    // 10) expert GEMM1 (gathered, gelu, rounded h out; B=w1 raw with in-frag CVT)
    gemm_tc<1, false, true, true, false, true, true><<<dim3(FF / BN, NPAIR / BM, EE), 256, GEMM_SMEM>>>(
        p_xn2r, w1, b1, nullptr, p_h, 0, FF, DD, p_pair, p_counts, p_offs,
        (size_t)DD * FF, (size_t)FF,
        nullptr, nullptr, nullptr, nullptr, nullptr, nullptr);
    // 11) expert GEMM2 (exact y out; B=w2 raw with in-frag CVT)
    gemm_tc<0, false, false, true, false, false, true><<<dim3(DD / BN, NPAIR / BM, EE), 256, GEMM_SMEM>>>(
        p_h, w2, b2, nullptr, p_y, 0, DD, FF, nullptr, p_counts, p_offs,
        (size_t)FF * DD, (size_t)DD,
        nullptr, nullptr, nullptr, nullptr, nullptr, nullptr);
    // 12) combine
    combine_kernel<<<TT, 256>>>(p_slot, p_tg, p_y, out);

    (void)in_sizes; (void)n_in; (void)out_size;
}